// round 9
// baseline (speedup 1.0000x reference)
#include <cuda_runtime.h>
#include <math.h>

#define BATCH 64
#define NG    32
#define CIN   128
#define COUT  128
#define LMAX  16
#define NR    (BATCH*LMAX*2)   // 2048 rows (b,m,ri) for stage C

// ---------------- scratch (device globals; no allocation allowed) ----------
__device__ float g_coef[(size_t)LMAX*NR*CIN];          // [l][r][i]
__device__ float g_chat[(size_t)LMAX*NR*COUT];         // [l][r][o]
__device__ float g_Qw[LMAX*LMAX*NG];                   // [l][m][j] * wj * s_l
__device__ float g_Qs[LMAX*LMAX*NG];                   // [l][m][j] * k_m
__device__ float g_cosT[LMAX*NG];                      // [m][p]
__device__ float g_sinT[LMAX*NG];

// smem layouts (floats): F/G tile 16448 | Q table 4096 | sc 256 | ss 256
#define SM_TILE_F2   8224          // 32 mr-rows * 257 (256 + 1 pad) float2
#define SM_Q_OFF     16448
#define SM_SC_OFF    (SM_Q_OFF + 4096)
#define SM_SS_OFF    (SM_SC_OFF + 256)
#define SM_TOTAL_B   ((SM_SS_OFF + 256) * 4)   // 84224 bytes

// ---------------- init: Legendre + trig tables, fp32, 512-way parallel -----
__global__ void init_tables() {
    int t = threadIdx.x;                  // 0..511
    int m = t >> 5, j = t & 31;           // one thread per (m, j)
    float sx, cx;
    sincospif((j + 0.5f) / NG, &sx, &cx);
    float wj = sx * ((float)M_PI / NG) * (2.0f * (float)M_PI / NG);

    for (int l = 0; l < m; l++) {
        g_Qw[(l*LMAX + m)*NG + j] = 0.f;
        g_Qs[(l*LMAX + m)*NG + j] = 0.f;
    }

    float Pmm = 1.0f, invf = 1.0f;
    for (int mm = 1; mm <= m; mm++) Pmm = -(2.0f*mm - 1.0f) * sx * Pmm;
    for (int tt = 1; tt <= 2*m; tt++) invf /= (float)tt;
    float rat = invf;
    float pl_2 = 0.0f, pl_1 = 0.0f, pl = 0.0f;
    const float inv4pi = 1.0f / (4.0f * (float)M_PI);
    for (int l = m; l < LMAX; l++) {
        if (l == m)        pl = Pmm;
        else if (l == m+1) pl = (2.0f*m + 1.0f) * cx * Pmm;
        else               pl = ((2.0f*l - 1.0f)*cx*pl_1 - (l + m - 1.0f)*pl_2) / (float)(l - m);
        float Nlm = sqrtf((2.0f*l + 1.0f) * inv4pi * rat);
        float q   = Nlm * pl;
        float sl  = 2.0f*(float)M_PI * sqrtf(4.0f*(float)M_PI / (2.0f*l + 1.0f));
        float km  = (m == 0) ? 1.0f : 2.0f;
        g_Qw[(l*LMAX + m)*NG + j] = q * wj * sl;
        g_Qs[(l*LMAX + m)*NG + j] = q * km;
        pl_2 = pl_1; pl_1 = pl;
        rat *= (float)(l + 1 - m) / (float)(l + 1 + m);
    }

    float sa, ca;
    sincospif(2.0f * (float)m * (float)j / (float)NG, &sa, &ca);
    g_cosT[m*NG + j] = ca;
    g_sinT[m*NG + j] = sa;
}

// ---------------- AB: fused real DFT (phi) + Legendre analysis (theta) -----
// block = (cg 0..7, b 0..63), 256 threads, 16 channels per block
__global__ void __launch_bounds__(256) kAB(const float* __restrict__ in) {
    extern __shared__ float sm[];
    float2* F_s = (float2*)sm;            // [mr:32][j*8+c2:256 (+1 pad)]
    float*  Qw_s = sm + SM_Q_OFF;         // [m][l][j<16]
    float*  sc = sm + SM_SC_OFF;          // [m][p<16]
    float*  ss = sm + SM_SS_OFF;

    int t = threadIdx.x;
    int cg = blockIdx.x, b = blockIdx.y;

    for (int q = t; q < 4096; q += 256) {
        int m = q >> 8, l = (q >> 4) & 15, j = q & 15;
        Qw_s[q] = g_Qw[(l*LMAX + m)*NG + j];
    }
    {
        int m = t >> 4, p = t & 15;
        sc[t] = g_cosT[m*NG + p];
        ss[t] = g_sinT[m*NG + p];
    }
    __syncthreads();

    // ---- stage 1: phi DFT (half-split), thread = (j, c2) ----
    {
        int j = t >> 3, c2 = t & 7;
        const float2* src = (const float2*)in
            + (((size_t)b*NG + j)*NG)*64 + cg*8 + c2;
        float2 u[16], v[16];
#pragma unroll
        for (int p = 0; p < 16; p++) {
            float2 a = src[p*64], c = src[(p+16)*64];
            u[p] = make_float2(a.x + c.x, a.y + c.y);
            v[p] = make_float2(a.x - c.x, a.y - c.y);
        }
#pragma unroll
        for (int m = 0; m < 16; m++) {
            float2 fr = make_float2(0.f,0.f), fi = make_float2(0.f,0.f);
#pragma unroll
            for (int p = 0; p < 16; p++) {
                float c = sc[m*16 + p], s = ss[m*16 + p];
                float2 x = (m & 1) ? v[p] : u[p];
                fr.x += x.x*c; fr.y += x.y*c;
                fi.x -= x.x*s; fi.y -= x.y*s;
            }
            F_s[(2*m    )*257 + j*8 + c2] = fr;
            F_s[(2*m + 1)*257 + j*8 + c2] = fi;
        }
    }
    __syncthreads();

    // ---- stage 2: Legendre quadrature with reflection, thread = (mr, c2) --
    {
        int mr = t >> 3, c2 = t & 7;
        int m = mr >> 1, ri = mr & 1;
        float sgn = (m & 1) ? -1.f : 1.f;
        float2 u[16], v[16];
#pragma unroll
        for (int j = 0; j < 16; j++) {
            float2 a = F_s[mr*257 + j*8 + c2];
            float2 c = F_s[mr*257 + (31-j)*8 + c2];
            u[j] = make_float2(a.x + sgn*c.x, a.y + sgn*c.y);
            v[j] = make_float2(a.x - sgn*c.x, a.y - sgn*c.y);
        }
        const float* q = Qw_s + m*256;
        float2* Cout = (float2*)g_coef;
        size_t r = ((size_t)b*16 + m)*2 + ri;
#pragma unroll
        for (int l = 0; l < 16; l++) {
            float2 acc = make_float2(0.f,0.f);
#pragma unroll
            for (int j = 0; j < 16; j++) {
                float qv = q[l*16 + j];
                float2 f = (l & 1) ? v[j] : u[j];
                acc.x += qv*f.x; acc.y += qv*f.y;
            }
            Cout[((size_t)l*NR + r)*64 + cg*8 + c2] = acc;
        }
    }
}

// ---------------- C: per-degree channel mix, double-buffered ---------------
__global__ void __launch_bounds__(256, 2) kC(const float* __restrict__ w) {
    int l = blockIdx.y, mt = blockIdx.x;  // 16 x 16
    const float* A = g_coef + ((size_t)l*NR + (size_t)mt*128)*CIN;
    const float* B = w + l*COUT;          // w[i][l][o], k-stride = LMAX*COUT
    float* C = g_chat + ((size_t)l*NR + (size_t)mt*128)*COUT;

    __shared__ float As[2][16][132];
    __shared__ float Bs[2][16][128];
    int tid = threadIdx.x;
    int tx = tid & 15, ty = tid >> 4;
    float acc[8][8] = {};

    // preload buffer 0
#pragma unroll
    for (int e = 0; e < 8; e++) {
        int lin = tid + e*256;
        int r = lin >> 4, k = lin & 15;
        As[0][k][r] = A[r*CIN + k];
        int kk = lin >> 7, o = lin & 127;
        Bs[0][kk][o] = B[(size_t)kk * (LMAX*COUT) + o];
    }
    __syncthreads();

    for (int it = 0; it < 8; it++) {
        int cur = it & 1;
        if (it < 7) {
            int k0 = (it + 1) * 16, nxt = cur ^ 1;
#pragma unroll
            for (int e = 0; e < 8; e++) {
                int lin = tid + e*256;
                int r = lin >> 4, k = lin & 15;
                As[nxt][k][r] = A[r*CIN + k0 + k];
                int kk = lin >> 7, o = lin & 127;
                Bs[nxt][kk][o] = B[(size_t)(k0 + kk) * (LMAX*COUT) + o];
            }
        }
#pragma unroll
        for (int k = 0; k < 16; k++) {
            float4 a0 = *(const float4*)&As[cur][k][ty*8];
            float4 a1 = *(const float4*)&As[cur][k][ty*8 + 4];
            float4 b0 = *(const float4*)&Bs[cur][k][tx*8];
            float4 b1 = *(const float4*)&Bs[cur][k][tx*8 + 4];
            float av[8] = {a0.x,a0.y,a0.z,a0.w,a1.x,a1.y,a1.z,a1.w};
            float bv[8] = {b0.x,b0.y,b0.z,b0.w,b1.x,b1.y,b1.z,b1.w};
#pragma unroll
            for (int i2 = 0; i2 < 8; i2++)
#pragma unroll
                for (int j2 = 0; j2 < 8; j2++)
                    acc[i2][j2] += av[i2] * bv[j2];
        }
        __syncthreads();
    }
#pragma unroll
    for (int i2 = 0; i2 < 8; i2++) {
        *(float4*)&C[(ty*8 + i2)*COUT + tx*8]     =
            make_float4(acc[i2][0], acc[i2][1], acc[i2][2], acc[i2][3]);
        *(float4*)&C[(ty*8 + i2)*COUT + tx*8 + 4] =
            make_float4(acc[i2][4], acc[i2][5], acc[i2][6], acc[i2][7]);
    }
}

// ---------------- DE: fused Legendre synthesis + inverse DFT + bias --------
// block = (cg 0..7, b 0..63), 256 threads, 16 channels per block
__global__ void __launch_bounds__(256) kDE(const float* __restrict__ bias,
                                           float* __restrict__ out) {
    extern __shared__ float sm[];
    float2* G_s = (float2*)sm;            // [mr:32][j*8+c2:256 (+1 pad)]
    float*  Qs_s = sm + SM_Q_OFF;         // [m][l][j<16]
    float*  sc = sm + SM_SC_OFF;          // [m][p<16]
    float*  ss = sm + SM_SS_OFF;

    int t = threadIdx.x;
    int cg = blockIdx.x, b = blockIdx.y;

    for (int q = t; q < 4096; q += 256) {
        int m = q >> 8, l = (q >> 4) & 15, j = q & 15;
        Qs_s[q] = g_Qs[(l*LMAX + m)*NG + j];
    }
    {
        int m = t >> 4, p = t & 15;
        sc[t] = g_cosT[m*NG + p];
        ss[t] = g_sinT[m*NG + p];
    }
    __syncthreads();

    // ---- stage 1: Legendre synthesis with reflection, thread = (mr, c2) ---
    {
        int mr = t >> 3, c2 = t & 7;
        int m = mr >> 1, ri = mr & 1;
        size_t r = ((size_t)b*16 + m)*2 + ri;
        float2 ch[16];
        const float2* src = (const float2*)g_chat;
#pragma unroll
        for (int l = 0; l < 16; l++)
            ch[l] = src[((size_t)l*NR + r)*64 + cg*8 + c2];
        float sgn = (m & 1) ? -1.f : 1.f;
        const float* q = Qs_s + m*256;
#pragma unroll
        for (int j = 0; j < 16; j++) {
            float2 a0 = make_float2(0.f,0.f), a1 = make_float2(0.f,0.f);
#pragma unroll
            for (int l = 0; l < 16; l++) {
                float qv = q[l*16 + j];
                if (l & 1) { a1.x += qv*ch[l].x; a1.y += qv*ch[l].y; }
                else       { a0.x += qv*ch[l].x; a0.y += qv*ch[l].y; }
            }
            G_s[mr*257 + j*8 + c2]      = make_float2(a0.x + a1.x, a0.y + a1.y);
            G_s[mr*257 + (31-j)*8 + c2] = make_float2(sgn*(a0.x - a1.x),
                                                      sgn*(a0.y - a1.y));
        }
    }
    __syncthreads();

    // ---- stage 2: inverse phi DFT (half-split) + bias, thread = (j, c2) ---
    {
        int j = t >> 3, c2 = t & 7;
        float2 gr[16], gi[16];
#pragma unroll
        for (int m = 0; m < 16; m++) {
            gr[m] = G_s[(2*m    )*257 + j*8 + c2];
            gi[m] = G_s[(2*m + 1)*257 + j*8 + c2];
        }
        float2 bv = ((const float2*)bias)[cg*8 + c2];
        float2* dst = (float2*)out + (((size_t)b*NG + j)*NG)*64 + cg*8 + c2;
#pragma unroll
        for (int p = 0; p < 16; p++) {
            float2 E = make_float2(0.f,0.f), O = make_float2(0.f,0.f);
#pragma unroll
            for (int m = 0; m < 16; m++) {
                float c = sc[m*16 + p], s = ss[m*16 + p];
                if (m & 1) {
                    O.x += gr[m].x*c - gi[m].x*s;
                    O.y += gr[m].y*c - gi[m].y*s;
                } else {
                    E.x += gr[m].x*c - gi[m].x*s;
                    E.y += gr[m].y*c - gi[m].y*s;
                }
            }
            dst[p*64]      = make_float2(bv.x + E.x + O.x, bv.y + E.y + O.y);
            dst[(p+16)*64] = make_float2(bv.x + E.x - O.x, bv.y + E.y - O.y);
        }
    }
}

extern "C" void kernel_launch(void* const* d_in, const int* in_sizes, int n_in,
                              void* d_out, int out_size) {
    const float* in   = (const float*)d_in[0];
    const float* w    = (const float*)d_in[1];
    const float* bias = (const float*)d_in[2];
    float* out = (float*)d_out;

    cudaFuncSetAttribute(kAB, cudaFuncAttributeMaxDynamicSharedMemorySize, SM_TOTAL_B);
    cudaFuncSetAttribute(kDE, cudaFuncAttributeMaxDynamicSharedMemorySize, SM_TOTAL_B);

    init_tables<<<1, 512>>>();
    kAB<<<dim3(8, BATCH), 256, SM_TOTAL_B>>>(in);
    kC<<<dim3(16, LMAX), 256>>>(w);
    kDE<<<dim3(8, BATCH), 256, SM_TOTAL_B>>>(bias, out);
}

// round 10
// speedup vs baseline: 1.0985x; 1.0985x over previous
#include <cuda_runtime.h>
#include <math.h>

#define BATCH 64
#define NG    32
#define CIN   128
#define COUT  128
#define LMAX  16
#define NR    (BATCH*LMAX*2)   // 2048 rows (b,m,ri)

// ---------------- scratch (device globals; no allocation allowed) ----------
__device__ float g_F[(size_t)BATCH*LMAX*2*NG*CIN];     // [b][m][ri][j][i]
// coef/chat layout: [l][m][ri][b][c]  -> valid region per l = first (l+1)*128 rows
__device__ float g_coef[(size_t)LMAX*2048*CIN];
__device__ float g_chat[(size_t)LMAX*2048*COUT];
__device__ float g_G[(size_t)BATCH*NG*LMAX*2*COUT];    // [b][j][m][ri][o]
__device__ float g_Qw[LMAX*LMAX*NG];                   // [l][m][j] * wj * s_l
__device__ float g_Qs[LMAX*LMAX*NG];                   // [l][m][j] * k_m
__device__ float g_cosT[LMAX*NG];                      // [m][p]
__device__ float g_sinT[LMAX*NG];

// ---------------- init: Legendre + trig tables, fp32, 512-way parallel -----
__global__ void init_tables() {
    int t = threadIdx.x;                  // 0..511
    int m = t >> 5, j = t & 31;           // one thread per (m, j)
    float sx, cx;
    sincospif((j + 0.5f) / NG, &sx, &cx);
    float wj = sx * ((float)M_PI / NG) * (2.0f * (float)M_PI / NG);

    for (int l = 0; l < m; l++) {
        g_Qw[(l*LMAX + m)*NG + j] = 0.f;
        g_Qs[(l*LMAX + m)*NG + j] = 0.f;
    }

    float Pmm = 1.0f, invf = 1.0f;
    for (int mm = 1; mm <= m; mm++) Pmm = -(2.0f*mm - 1.0f) * sx * Pmm;
    for (int tt = 1; tt <= 2*m; tt++) invf /= (float)tt;
    float rat = invf;
    float pl_2 = 0.0f, pl_1 = 0.0f, pl = 0.0f;
    const float inv4pi = 1.0f / (4.0f * (float)M_PI);
    for (int l = m; l < LMAX; l++) {
        if (l == m)        pl = Pmm;
        else if (l == m+1) pl = (2.0f*m + 1.0f) * cx * Pmm;
        else               pl = ((2.0f*l - 1.0f)*cx*pl_1 - (l + m - 1.0f)*pl_2) / (float)(l - m);
        float Nlm = sqrtf((2.0f*l + 1.0f) * inv4pi * rat);
        float q   = Nlm * pl;
        float sl  = 2.0f*(float)M_PI * sqrtf(4.0f*(float)M_PI / (2.0f*l + 1.0f));
        float km  = (m == 0) ? 1.0f : 2.0f;
        g_Qw[(l*LMAX + m)*NG + j] = q * wj * sl;
        g_Qs[(l*LMAX + m)*NG + j] = q * km;
        pl_2 = pl_1; pl_1 = pl;
        rat *= (float)(l + 1 - m) / (float)(l + 1 + m);
    }

    float sa, ca;
    sincospif(2.0f * (float)m * (float)j / (float)NG, &sa, &ca);
    g_cosT[m*NG + j] = ca;
    g_sinT[m*NG + j] = sa;
}

// ---------------- A: real DFT over phi (half-split), float2 channels -------
__global__ void __launch_bounds__(64) kA(const float* __restrict__ in) {
    int bj = blockIdx.x;                  // b*32 + j (theta)
    int b = bj >> 5, j = bj & 31;
    int t = threadIdx.x;                  // channel pair 0..63
    __shared__ float sc[16][16], ss[16][16];
    for (int q = t; q < 256; q += 64) {
        int m = q >> 4, p = q & 15;
        sc[m][p] = g_cosT[m*NG + p];
        ss[m][p] = g_sinT[m*NG + p];
    }
    __syncthreads();

    const float2* src = (const float2*)in + (size_t)bj * NG * 64 + t;
    float2 xe[16], xo[16];
#pragma unroll
    for (int p = 0; p < 16; p++) {
        float2 a = src[p*64], c = src[(p+16)*64];
        xe[p] = make_float2(a.x + c.x, a.y + c.y);
        xo[p] = make_float2(a.x - c.x, a.y - c.y);
    }

    float2* Fout = (float2*)g_F;
#pragma unroll
    for (int m = 0; m < 16; m++) {
        float2 fr = make_float2(0.f, 0.f), fi = make_float2(0.f, 0.f);
#pragma unroll
        for (int p = 0; p < 16; p++) {
            float c = sc[m][p], s = ss[m][p];
            float2 x = (m & 1) ? xo[p] : xe[p];
            fr.x += x.x*c; fr.y += x.y*c;
            fi.x -= x.x*s; fi.y -= x.y*s;
        }
        size_t base = ((((size_t)b*16 + m)*2 + 0)*NG + j)*64 + t;
        Fout[base]          = fr;
        Fout[base + NG*64]  = fi;   // ri=1
    }
}

// ---------------- B: Legendre analysis with reflection symmetry ------------
// writes coef in [l][m][ri][b] row order; skips l < m (zero rows never read)
__global__ void __launch_bounds__(64) kB() {
    int r = blockIdx.x;                   // (b*16+m)*2+ri
    int b = r >> 5, m = (r >> 1) & 15, ri = r & 1;
    int t = threadIdx.x;
    __shared__ float sq[16][16];          // Qw[l][m][j], j<16
    for (int q = t; q < 256; q += 64) {
        int l = q >> 4, j = q & 15;
        sq[l][j] = g_Qw[(l*LMAX + m)*NG + j];
    }
    __syncthreads();

    const float2* src = (const float2*)g_F + (size_t)r * NG * 64 + t;
    float2 fe[16], fo[16];
#pragma unroll
    for (int j = 0; j < 16; j++) {
        float2 a = src[j*64], c = src[(31-j)*64];
        fe[j] = make_float2(a.x + c.x, a.y + c.y);
        fo[j] = make_float2(a.x - c.x, a.y - c.y);
    }

    float2* Cout = (float2*)g_coef;
    size_t rowbase = (size_t)(m*2 + ri)*64 + b;   // within-l row offset
    if ((m & 1) == 0) {
#pragma unroll
        for (int l = 0; l < 16; l++) {
            if (l < m) continue;
            float2 acc = make_float2(0.f, 0.f);
#pragma unroll
            for (int j = 0; j < 16; j++) {
                float q = sq[l][j];
                float2 f = (l & 1) ? fo[j] : fe[j];
                acc.x += q*f.x; acc.y += q*f.y;
            }
            Cout[((size_t)l*2048 + rowbase)*64 + t] = acc;
        }
    } else {
#pragma unroll
        for (int l = 0; l < 16; l++) {
            if (l < m) continue;
            float2 acc = make_float2(0.f, 0.f);
#pragma unroll
            for (int j = 0; j < 16; j++) {
                float q = sq[l][j];
                float2 f = (l & 1) ? fe[j] : fo[j];
                acc.x += q*f.x; acc.y += q*f.y;
            }
            Cout[((size_t)l*2048 + rowbase)*64 + t] = acc;
        }
    }
}

// ---------------- C: per-degree channel mix, triangular, double-buffered ---
// degree l has (l+1)*128 valid rows (m <= l contiguous in new layout)
__global__ void __launch_bounds__(256, 2) kC(const float* __restrict__ w) {
    int l = blockIdx.y, mt = blockIdx.x;
    if (mt > l) return;                   // zero region: skip
    const float* A = g_coef + ((size_t)l*2048 + (size_t)mt*128)*CIN;
    const float* B = w + l*COUT;          // w[i][l][o], k-stride = LMAX*COUT
    float* C = g_chat + ((size_t)l*2048 + (size_t)mt*128)*COUT;

    __shared__ float As[2][16][132];
    __shared__ float Bs[2][16][128];
    int tid = threadIdx.x;
    int tx = tid & 15, ty = tid >> 4;
    float acc[8][8] = {};

#pragma unroll
    for (int e = 0; e < 8; e++) {
        int lin = tid + e*256;
        int r = lin >> 4, k = lin & 15;
        As[0][k][r] = A[r*CIN + k];
        int kk = lin >> 7, o = lin & 127;
        Bs[0][kk][o] = B[(size_t)kk * (LMAX*COUT) + o];
    }
    __syncthreads();

    for (int it = 0; it < 8; it++) {
        int cur = it & 1;
        if (it < 7) {
            int k0 = (it + 1) * 16, nxt = cur ^ 1;
#pragma unroll
            for (int e = 0; e < 8; e++) {
                int lin = tid + e*256;
                int r = lin >> 4, k = lin & 15;
                As[nxt][k][r] = A[r*CIN + k0 + k];
                int kk = lin >> 7, o = lin & 127;
                Bs[nxt][kk][o] = B[(size_t)(k0 + kk) * (LMAX*COUT) + o];
            }
        }
#pragma unroll
        for (int k = 0; k < 16; k++) {
            float4 a0 = *(const float4*)&As[cur][k][ty*8];
            float4 a1 = *(const float4*)&As[cur][k][ty*8 + 4];
            float4 b0 = *(const float4*)&Bs[cur][k][tx*8];
            float4 b1 = *(const float4*)&Bs[cur][k][tx*8 + 4];
            float av[8] = {a0.x,a0.y,a0.z,a0.w,a1.x,a1.y,a1.z,a1.w};
            float bv[8] = {b0.x,b0.y,b0.z,b0.w,b1.x,b1.y,b1.z,b1.w};
#pragma unroll
            for (int i2 = 0; i2 < 8; i2++)
#pragma unroll
                for (int j2 = 0; j2 < 8; j2++)
                    acc[i2][j2] += av[i2] * bv[j2];
        }
        __syncthreads();
    }
#pragma unroll
    for (int i2 = 0; i2 < 8; i2++) {
        *(float4*)&C[(ty*8 + i2)*COUT + tx*8]     =
            make_float4(acc[i2][0], acc[i2][1], acc[i2][2], acc[i2][3]);
        *(float4*)&C[(ty*8 + i2)*COUT + tx*8 + 4] =
            make_float4(acc[i2][4], acc[i2][5], acc[i2][6], acc[i2][7]);
    }
}

// ---------------- D: Legendre synthesis with reflection symmetry -----------
__global__ void __launch_bounds__(64) kD() {
    int r = blockIdx.x;                   // (b*16+m)*2+ri
    int ri = r & 1, m = (r >> 1) & 15, b = r >> 5;
    int t = threadIdx.x;
    __shared__ float sq[16][16];          // Qs[l][m][j], j<16 (incl. k_m)
    for (int q = t; q < 256; q += 64) {
        int l = q >> 4, j = q & 15;
        sq[l][j] = g_Qs[(l*LMAX + m)*NG + j];
    }
    __syncthreads();

    float2 ch[16];
    const float2* src = (const float2*)g_chat;
    size_t rowbase = (size_t)(m*2 + ri)*64 + b;
#pragma unroll
    for (int l = 0; l < 16; l++)
        ch[l] = (l >= m) ? src[((size_t)l*2048 + rowbase)*64 + t]
                         : make_float2(0.f, 0.f);

    float2* Gout = (float2*)g_G;
    size_t gbase = ((((size_t)b*NG)*16 + m)*2 + ri)*64 + t;
    const size_t jstride = (size_t)16*2*64;

    if ((m & 1) == 0) {
#pragma unroll
        for (int j = 0; j < 16; j++) {
            float2 Ge = make_float2(0.f,0.f), Go = make_float2(0.f,0.f);
#pragma unroll
            for (int l = 0; l < 16; l++) {
                float q = sq[l][j];
                if (l & 1) { Go.x += q*ch[l].x; Go.y += q*ch[l].y; }
                else       { Ge.x += q*ch[l].x; Ge.y += q*ch[l].y; }
            }
            Gout[gbase + (size_t)j*jstride]      = make_float2(Ge.x+Go.x, Ge.y+Go.y);
            Gout[gbase + (size_t)(31-j)*jstride] = make_float2(Ge.x-Go.x, Ge.y-Go.y);
        }
    } else {
#pragma unroll
        for (int j = 0; j < 16; j++) {
            float2 Ge = make_float2(0.f,0.f), Go = make_float2(0.f,0.f);
#pragma unroll
            for (int l = 0; l < 16; l++) {
                float q = sq[l][j];
                if (l & 1) { Ge.x += q*ch[l].x; Ge.y += q*ch[l].y; }
                else       { Go.x += q*ch[l].x; Go.y += q*ch[l].y; }
            }
            Gout[gbase + (size_t)j*jstride]      = make_float2(Ge.x+Go.x, Ge.y+Go.y);
            Gout[gbase + (size_t)(31-j)*jstride] = make_float2(Ge.x-Go.x, Ge.y-Go.y);
        }
    }
}

// ---------------- E: inverse real DFT over phi (half-split) + bias ---------
__global__ void __launch_bounds__(64) kE(const float* __restrict__ bias,
                                         float* __restrict__ out) {
    int bj = blockIdx.x;                  // b*32 + j (theta)
    int t = threadIdx.x;                  // channel pair
    __shared__ float sc[16][16], ss[16][16];
    for (int q = t; q < 256; q += 64) {
        int m = q >> 4, p = q & 15;
        sc[m][p] = g_cosT[m*NG + p];
        ss[m][p] = g_sinT[m*NG + p];
    }
    __syncthreads();

    float2 gr[16], gi[16];
    const float2* src = (const float2*)g_G + (size_t)bj * 16 * 2 * 64 + t;
#pragma unroll
    for (int m = 0; m < 16; m++) {
        gr[m] = src[(m*2 + 0)*64];
        gi[m] = src[(m*2 + 1)*64];
    }
    float2 bv = ((const float2*)bias)[t];
    float2* dst = (float2*)out + (size_t)bj * NG * 64 + t;
#pragma unroll
    for (int p = 0; p < 16; p++) {
        float2 E = make_float2(0.f,0.f), O = make_float2(0.f,0.f);
#pragma unroll
        for (int m = 0; m < 16; m++) {
            float c = sc[m][p], s = ss[m][p];
            if (m & 1) {
                O.x += gr[m].x*c - gi[m].x*s;
                O.y += gr[m].y*c - gi[m].y*s;
            } else {
                E.x += gr[m].x*c - gi[m].x*s;
                E.y += gr[m].y*c - gi[m].y*s;
            }
        }
        dst[p*64]      = make_float2(bv.x + E.x + O.x, bv.y + E.y + O.y);
        dst[(p+16)*64] = make_float2(bv.x + E.x - O.x, bv.y + E.y - O.y);
    }
}

extern "C" void kernel_launch(void* const* d_in, const int* in_sizes, int n_in,
                              void* d_out, int out_size) {
    const float* in   = (const float*)d_in[0];
    const float* w    = (const float*)d_in[1];
    const float* bias = (const float*)d_in[2];
    float* out = (float*)d_out;

    init_tables<<<1, 512>>>();
    kA<<<BATCH*NG, 64>>>(in);
    kB<<<NR, 64>>>();
    kC<<<dim3(16, LMAX), 256>>>(w);
    kD<<<NR, 64>>>();
    kE<<<BATCH*NG, 64>>>(bias, out);
}